// round 14
// baseline (speedup 1.0000x reference)
#include <cuda_runtime.h>
#include <cuda_bf16.h>
#include <cstdint>

// Problem constants
#define NB  4
#define NN  4096   // H*W
#define NC  256
#define NCP 128
#define KSPLIT 2

// Scratch (static __device__ arrays: the sanctioned no-alloc scratch mechanism).
static __device__ float          g_V  [NB * NN * NCP];       // fp32 V
static __device__ __nv_bfloat16  g_Khi[NB * NN * NCP];       // K split hi/lo  [b*NN+n][c]
static __device__ __nv_bfloat16  g_Klo[NB * NN * NCP];
static __device__ __nv_bfloat16  g_Qhi[NB * NN * NCP];       // Q split hi/lo
static __device__ __nv_bfloat16  g_Qlo[NB * NN * NCP];
static __device__ __nv_bfloat16  g_Vthi[NB * NCP * NN];      // V^T hi/lo  [b*NCP+c][n]
static __device__ __nv_bfloat16  g_Vtlo[NB * NCP * NN];
static __device__ __nv_bfloat16  g_Wth[4 * NCP * NC];        // W^T splits [sel][col][k]
static __device__ __nv_bfloat16  g_Wtl[4 * NCP * NC];
// split-KV partials: unnormalized O, row max m, row sum l
static __device__ float          g_Po[KSPLIT * NB * NN * NCP];
static __device__ float          g_Pm[KSPLIT * NB * NN];
static __device__ float          g_Pl[KSPLIT * NB * NN];

// ---- bf16 split + pack helpers ----
__device__ __forceinline__ void bsplit(float x, __nv_bfloat16& h, __nv_bfloat16& l) {
    h = __float2bfloat16(x);
    l = __float2bfloat16(x - __bfloat162float(h));
}
__device__ __forceinline__ uint32_t pk(__nv_bfloat16 a, __nv_bfloat16 b) {
    return (uint32_t)__bfloat16_as_ushort(a) | ((uint32_t)__bfloat16_as_ushort(b) << 16);
}
__device__ __forceinline__ uint32_t pkhi(float a, float b) {
    return pk(__float2bfloat16(a), __float2bfloat16(b));
}
__device__ __forceinline__ uint32_t pklo(float a, float b) {
    __nv_bfloat16 ha = __float2bfloat16(a), hb = __float2bfloat16(b);
    return pk(__float2bfloat16(a - __bfloat162float(ha)),
              __float2bfloat16(b - __bfloat162float(hb)));
}

// ---- warp MMA: m16n8k16, row.col, bf16 in, fp32 acc (baseline PTX, sm_80+) ----
__device__ __forceinline__ void mma_bf16(float c[4], uint32_t a0, uint32_t a1,
                                         uint32_t a2, uint32_t a3,
                                         uint32_t b0, uint32_t b1) {
    asm volatile("mma.sync.aligned.m16n8k16.row.col.f32.bf16.bf16.f32 "
        "{%0,%1,%2,%3}, {%4,%5,%6,%7}, {%8,%9}, {%0,%1,%2,%3};"
        : "+f"(c[0]), "+f"(c[1]), "+f"(c[2]), "+f"(c[3])
        : "r"(a0), "r"(a1), "r"(a2), "r"(a3), "r"(b0), "r"(b1));
}

#define SKS 72   // proj tile stride (unchanged)
#define KS2 136  // 128-wide K/Q tile stride
#define VS3 40   // 32-wide V tile stride

// ============================================================================
// Kernel 0: pre-split + transpose weights.
// ============================================================================
__global__ void wsplit_kernel(const float* __restrict__ Wk, const float* __restrict__ Wq,
                              const float* __restrict__ Wv, const float* __restrict__ Ws)
{
    const int sel = blockIdx.x;
    const float* W = (sel == 0) ? Wk : (sel == 1) ? Wq : (sel == 2) ? Wv : Ws;
    for (int idx = threadIdx.x; idx < NCP * NC; idx += blockDim.x) {
        int c = idx >> 8, k = idx & 255;
        __nv_bfloat16 h, l; bsplit(W[(size_t)k * NCP + c], h, l);
        g_Wth[sel * NCP * NC + idx] = h;
        g_Wtl[sel * NCP * NC + idx] = l;
    }
}

// ============================================================================
// Kernel 1: projections via bf16 mma 3-product split (unchanged from R13).
// ============================================================================
#define PRJ_SMEM (4 * 128 * SKS * 2)   // 73728 B

__global__ void __launch_bounds__(256) proj_kernel(
    const float* __restrict__ X,
    const float* __restrict__ bk, const float* __restrict__ bq,
    const float* __restrict__ bv, const float* __restrict__ bs,
    float* __restrict__ OutS)
{
    extern __shared__ __align__(16) char smraw[];
    __nv_bfloat16* sXh = (__nv_bfloat16*)smraw;
    __nv_bfloat16* sXl = sXh + 128 * SKS;
    __nv_bfloat16* sWh = sXl + 128 * SKS;
    __nv_bfloat16* sWl = sWh + 128 * SKS;

    const int sel = blockIdx.y;
    const float* bia = (sel == 0) ? bk : (sel == 1) ? bq : (sel == 2) ? bv : bs;
    const __nv_bfloat16* Wh = g_Wth + sel * NCP * NC;
    const __nv_bfloat16* Wl = g_Wtl + sel * NCP * NC;

    const int tid = threadIdx.x;
    const int lane = tid & 31, w = tid >> 5;
    const int g = lane >> 2, q4 = lane & 3;
    const int wm = w & 1, wn = w >> 1;
    const int rowBase = blockIdx.x * 128;

    float C[4][4][4];
#pragma unroll
    for (int mi = 0; mi < 4; mi++)
#pragma unroll
        for (int ni = 0; ni < 4; ni++)
#pragma unroll
            for (int e = 0; e < 4; e++) C[mi][ni][e] = 0.f;

    for (int kp = 0; kp < 4; kp++) {
        __syncthreads();
#pragma unroll
        for (int u = 0; u < 8; u++) {
            int idx = tid + u * 256;
            int r = idx >> 4, c4 = idx & 15;
            float4 v = *(const float4*)(X + (size_t)(rowBase + r) * NC + kp * 64 + c4 * 4);
            __nv_bfloat16 h0,l0,h1,l1,h2,l2,h3,l3;
            bsplit(v.x,h0,l0); bsplit(v.y,h1,l1); bsplit(v.z,h2,l2); bsplit(v.w,h3,l3);
            int so = r * SKS + c4 * 4;
            *(uint2*)(sXh + so) = make_uint2(pk(h0,h1), pk(h2,h3));
            *(uint2*)(sXl + so) = make_uint2(pk(l0,l1), pk(l2,l3));
        }
#pragma unroll
        for (int u = 0; u < 4; u++) {
            int idx = tid + u * 256;
            int col = idx >> 3, k8 = idx & 7;
            int go = col * NC + kp * 64 + k8 * 8;
            int so = col * SKS + k8 * 8;
            *(uint4*)(sWh + so) = *(const uint4*)(Wh + go);
            *(uint4*)(sWl + so) = *(const uint4*)(Wl + go);
        }
        __syncthreads();

#pragma unroll
        for (int kc = 0; kc < 4; kc++) {
            const int k0 = kc * 16 + q4 * 2;
            uint32_t Bh[4][2], Bl[4][2];
#pragma unroll
            for (int ni = 0; ni < 4; ni++) {
                int col = wn * 32 + ni * 8 + g;
                Bh[ni][0] = *(const uint32_t*)(sWh + col * SKS + k0);
                Bh[ni][1] = *(const uint32_t*)(sWh + col * SKS + k0 + 8);
                Bl[ni][0] = *(const uint32_t*)(sWl + col * SKS + k0);
                Bl[ni][1] = *(const uint32_t*)(sWl + col * SKS + k0 + 8);
            }
#pragma unroll
            for (int mi = 0; mi < 4; mi++) {
                int row = wm * 64 + mi * 16 + g;
                uint32_t a0 = *(const uint32_t*)(sXh + row * SKS + k0);
                uint32_t a1 = *(const uint32_t*)(sXh + (row + 8) * SKS + k0);
                uint32_t a2 = *(const uint32_t*)(sXh + row * SKS + k0 + 8);
                uint32_t a3 = *(const uint32_t*)(sXh + (row + 8) * SKS + k0 + 8);
                uint32_t l0 = *(const uint32_t*)(sXl + row * SKS + k0);
                uint32_t l1 = *(const uint32_t*)(sXl + (row + 8) * SKS + k0);
                uint32_t l2 = *(const uint32_t*)(sXl + row * SKS + k0 + 8);
                uint32_t l3 = *(const uint32_t*)(sXl + (row + 8) * SKS + k0 + 8);
#pragma unroll
                for (int ni = 0; ni < 4; ni++)
                    mma_bf16(C[mi][ni], a0, a1, a2, a3, Bh[ni][0], Bh[ni][1]); // hh
#pragma unroll
                for (int ni = 0; ni < 4; ni++)
                    mma_bf16(C[mi][ni], a0, a1, a2, a3, Bl[ni][0], Bl[ni][1]); // hl
#pragma unroll
                for (int ni = 0; ni < 4; ni++)
                    mma_bf16(C[mi][ni], l0, l1, l2, l3, Bh[ni][0], Bh[ni][1]); // lh
            }
        }
    }

#pragma unroll
    for (int ni = 0; ni < 4; ni++) {
        int col = wn * 32 + ni * 8 + q4 * 2;
        float2 bb = *(const float2*)(bia + col);
#pragma unroll
        for (int mi = 0; mi < 4; mi++) {
            int row = rowBase + wm * 64 + mi * 16 + g;
            float v0 = C[mi][ni][0] + bb.x, v1 = C[mi][ni][1] + bb.y;
            float v2 = C[mi][ni][2] + bb.x, v3 = C[mi][ni][3] + bb.y;
            size_t o0 = (size_t)row * NCP + col;
            size_t o1 = (size_t)(row + 8) * NCP + col;
            if (sel <= 1) {
                __nv_bfloat16* Yh = (sel == 0) ? g_Khi : g_Qhi;
                __nv_bfloat16* Yl = (sel == 0) ? g_Klo : g_Qlo;
                __nv_bfloat16 h0,l0,h1,l1;
                bsplit(v0,h0,l0); bsplit(v1,h1,l1);
                *(uint32_t*)(Yh + o0) = pk(h0,h1);
                *(uint32_t*)(Yl + o0) = pk(l0,l1);
                bsplit(v2,h0,l0); bsplit(v3,h1,l1);
                *(uint32_t*)(Yh + o1) = pk(h0,h1);
                *(uint32_t*)(Yl + o1) = pk(l0,l1);
            } else {
                float* Yf = (sel == 2) ? g_V : OutS;
                *(float2*)(Yf + o0) = make_float2(v0, v1);
                *(float2*)(Yf + o1) = make_float2(v2, v3);
            }
        }
    }
}

// ============================================================================
// Kernel 2: V -> V^T bf16 hi/lo.
// ============================================================================
__global__ void vt_kernel()
{
    __shared__ float t[32][33];
    const int b  = blockIdx.z;
    const int n0 = blockIdx.x * 32;
    const int c0 = blockIdx.y * 32;
    const int tx = threadIdx.x, ty = threadIdx.y;   // 32 x 8
#pragma unroll
    for (int u = 0; u < 4; u++)
        t[ty * 4 + u][tx] = g_V[((size_t)b * NN + n0 + ty * 4 + u) * NCP + c0 + tx];
    __syncthreads();
#pragma unroll
    for (int u = 0; u < 4; u++) {
        float x = t[tx][ty * 4 + u];
        __nv_bfloat16 h, l; bsplit(x, h, l);
        size_t off = ((size_t)b * NCP + c0 + ty * 4 + u) * NN + n0 + tx;
        g_Vthi[off] = h;
        g_Vtlo[off] = l;
    }
}

// ============================================================================
// Kernel 3: flash attention, split-KV, 3 CTAs/SM.
//   grid (64 rowblocks, NB, KSPLIT); CTA = 64 K-rows, 128 thr / 4 warps,
//   chunks of 32 Q-cols over this CTA's half of the n-range. Emits
//   unnormalized partial (O, m, l). smem 72.7KB + regs<=170 -> 3 CTAs/SM.
// ============================================================================
#define FL_SMEM ((2 * 64 * KS2 + 2 * 32 * KS2 + 2 * 128 * VS3) * 2)   // 72704 B

__global__ void __launch_bounds__(128, 3) flash_kernel()
{
    extern __shared__ __align__(16) char smraw[];
    __nv_bfloat16* sKh = (__nv_bfloat16*)smraw;          // [64][KS2]
    __nv_bfloat16* sKl = sKh + 64 * KS2;
    __nv_bfloat16* sQh = sKl + 64 * KS2;                 // [32][KS2]
    __nv_bfloat16* sQl = sQh + 32 * KS2;
    __nv_bfloat16* sVh = sQl + 32 * KS2;                 // [128][VS3]
    __nv_bfloat16* sVl = sVh + 128 * VS3;

    const int tid = threadIdx.x;
    const int lane = tid & 31, w = tid >> 5;
    const int g = lane >> 2, t = lane & 3;
    const int mt = blockIdx.x, b = blockIdx.y, ksp = blockIdx.z;
    const int nbase = ksp * (NN / KSPLIT);

    // K tile once (64 rows x 128 d, hi+lo)
#pragma unroll
    for (int u = 0; u < 8; u++) {
        int idx = tid + u * 128;
        int r = idx >> 4, c8 = idx & 15;
        size_t go = ((size_t)(b * NN + mt * 64 + r)) * NCP + c8 * 8;
        int so = r * KS2 + c8 * 8;
        *(uint4*)(sKh + so) = *(const uint4*)(g_Khi + go);
        *(uint4*)(sKl + so) = *(const uint4*)(g_Klo + go);
    }

    const int rowA = w * 16 + g;

    float Co[16][4];
#pragma unroll
    for (int ci = 0; ci < 16; ci++)
#pragma unroll
        for (int e = 0; e < 4; e++) Co[ci][e] = 0.f;
    float m0 = -1e30f, m1 = -1e30f, l0s = 0.f, l1s = 0.f;

    for (int ch = 0; ch < (NN / KSPLIT) / 32; ch++) {
        const int n0 = nbase + ch * 32;
        __syncthreads();
        // Q chunk: 32 rows x 128 d
#pragma unroll
        for (int u = 0; u < 4; u++) {
            int idx = tid + u * 128;
            int r = idx >> 4, c8 = idx & 15;
            size_t go = ((size_t)(b * NN + n0 + r)) * NCP + c8 * 8;
            int so = r * KS2 + c8 * 8;
            *(uint4*)(sQh + so) = *(const uint4*)(g_Qhi + go);
            *(uint4*)(sQl + so) = *(const uint4*)(g_Qlo + go);
        }
        // V chunk: 128 c'-rows x 32 n
#pragma unroll
        for (int u = 0; u < 4; u++) {
            int idx = tid + u * 128;
            int r = idx >> 2, c8 = idx & 3;
            size_t go = ((size_t)(b * NCP + r)) * NN + n0 + c8 * 8;
            int so = r * VS3 + c8 * 8;
            *(uint4*)(sVh + so) = *(const uint4*)(g_Vthi + go);
            *(uint4*)(sVl + so) = *(const uint4*)(g_Vtlo + go);
        }
        __syncthreads();

        // ---- S tile 16x32: passes hh -> lh(cached bh) -> hl ----
        float Cs[4][4];
#pragma unroll
        for (int ni = 0; ni < 4; ni++)
#pragma unroll
            for (int e = 0; e < 4; e++) Cs[ni][e] = 0.f;
#pragma unroll
        for (int kc = 0; kc < 8; kc++) {
            const int k0 = kc * 16 + t * 2;
            uint32_t a0 = *(const uint32_t*)(sKh + rowA * KS2 + k0);
            uint32_t a1 = *(const uint32_t*)(sKh + (rowA + 8) * KS2 + k0);
            uint32_t a2 = *(const uint32_t*)(sKh + rowA * KS2 + k0 + 8);
            uint32_t a3 = *(const uint32_t*)(sKh + (rowA + 8) * KS2 + k0 + 8);
            uint32_t e0 = *(const uint32_t*)(sKl + rowA * KS2 + k0);
            uint32_t e1 = *(const uint32_t*)(sKl + (rowA + 8) * KS2 + k0);
            uint32_t e2 = *(const uint32_t*)(sKl + rowA * KS2 + k0 + 8);
            uint32_t e3 = *(const uint32_t*)(sKl + (rowA + 8) * KS2 + k0 + 8);
            uint32_t bhc[4][2];
#pragma unroll
            for (int ni = 0; ni < 4; ni++) {                   // hh (cache bh)
                int col = ni * 8 + g;
                bhc[ni][0] = *(const uint32_t*)(sQh + col * KS2 + k0);
                bhc[ni][1] = *(const uint32_t*)(sQh + col * KS2 + k0 + 8);
                mma_bf16(Cs[ni], a0, a1, a2, a3, bhc[ni][0], bhc[ni][1]);
            }
#pragma unroll
            for (int ni = 0; ni < 4; ni++)                     // lh (cached bh)
                mma_bf16(Cs[ni], e0, e1, e2, e3, bhc[ni][0], bhc[ni][1]);
#pragma unroll
            for (int ni = 0; ni < 4; ni++) {                   // hl
                int col = ni * 8 + g;
                uint32_t bl0 = *(const uint32_t*)(sQl + col * KS2 + k0);
                uint32_t bl1 = *(const uint32_t*)(sQl + col * KS2 + k0 + 8);
                mma_bf16(Cs[ni], a0, a1, a2, a3, bl0, bl1);
            }
        }

        // ---- online softmax ----
        float mx0 = -1e30f, mx1 = -1e30f;
#pragma unroll
        for (int ni = 0; ni < 4; ni++) {
            mx0 = fmaxf(mx0, fmaxf(Cs[ni][0], Cs[ni][1]));
            mx1 = fmaxf(mx1, fmaxf(Cs[ni][2], Cs[ni][3]));
        }
        mx0 = fmaxf(mx0, __shfl_xor_sync(0xffffffffu, mx0, 1));
        mx0 = fmaxf(mx0, __shfl_xor_sync(0xffffffffu, mx0, 2));
        mx1 = fmaxf(mx1, __shfl_xor_sync(0xffffffffu, mx1, 1));
        mx1 = fmaxf(mx1, __shfl_xor_sync(0xffffffffu, mx1, 2));
        float mn0 = fmaxf(m0, mx0), mn1 = fmaxf(m1, mx1);
        if (mn0 > m0 || mn1 > m1) {
            float al0 = __expf(m0 - mn0), al1 = __expf(m1 - mn1);
            l0s *= al0; l1s *= al1;
#pragma unroll
            for (int ci = 0; ci < 16; ci++) {
                Co[ci][0] *= al0; Co[ci][1] *= al0;
                Co[ci][2] *= al1; Co[ci][3] *= al1;
            }
            m0 = mn0; m1 = mn1;
        }
        float s0 = 0.f, s1 = 0.f;
#pragma unroll
        for (int ni = 0; ni < 4; ni++) {
            Cs[ni][0] = __expf(Cs[ni][0] - m0);
            Cs[ni][1] = __expf(Cs[ni][1] - m0);
            Cs[ni][2] = __expf(Cs[ni][2] - m1);
            Cs[ni][3] = __expf(Cs[ni][3] - m1);
            s0 += Cs[ni][0] + Cs[ni][1];
            s1 += Cs[ni][2] + Cs[ni][3];
        }
        s0 += __shfl_xor_sync(0xffffffffu, s0, 1);
        s0 += __shfl_xor_sync(0xffffffffu, s0, 2);
        s1 += __shfl_xor_sync(0xffffffffu, s1, 1);
        s1 += __shfl_xor_sync(0xffffffffu, s1, 2);
        l0s += s0;
        l1s += s1;

        // ---- P A-frags (C-frag == A-frag identity), chunk-local k range 32 ----
        uint32_t Ph[2][4], Pl[2][4];
#pragma unroll
        for (int ki = 0; ki < 2; ki++) {
            Ph[ki][0] = pkhi(Cs[2*ki  ][0], Cs[2*ki  ][1]);
            Ph[ki][1] = pkhi(Cs[2*ki  ][2], Cs[2*ki  ][3]);
            Ph[ki][2] = pkhi(Cs[2*ki+1][0], Cs[2*ki+1][1]);
            Ph[ki][3] = pkhi(Cs[2*ki+1][2], Cs[2*ki+1][3]);
            Pl[ki][0] = pklo(Cs[2*ki  ][0], Cs[2*ki  ][1]);
            Pl[ki][1] = pklo(Cs[2*ki  ][2], Cs[2*ki  ][3]);
            Pl[ki][2] = pklo(Cs[2*ki+1][0], Cs[2*ki+1][1]);
            Pl[ki][3] = pklo(Cs[2*ki+1][2], Cs[2*ki+1][3]);
        }

        // ---- O += P @ V: product-outer passes ----
#pragma unroll
        for (int ks = 0; ks < 2; ks++) {
            const int k0 = ks * 16 + t * 2;
#pragma unroll
            for (int ci = 0; ci < 16; ci++) {                  // PhVh
                int col = ci * 8 + g;
                uint32_t vh0 = *(const uint32_t*)(sVh + col * VS3 + k0);
                uint32_t vh1 = *(const uint32_t*)(sVh + col * VS3 + k0 + 8);
                mma_bf16(Co[ci], Ph[ks][0], Ph[ks][1], Ph[ks][2], Ph[ks][3], vh0, vh1);
            }
#pragma unroll
            for (int ci = 0; ci < 16; ci++) {                  // PhVl
                int col = ci * 8 + g;
                uint32_t vl0 = *(const uint32_t*)(sVl + col * VS3 + k0);
                uint32_t vl1 = *(const uint32_t*)(sVl + col * VS3 + k0 + 8);
                mma_bf16(Co[ci], Ph[ks][0], Ph[ks][1], Ph[ks][2], Ph[ks][3], vl0, vl1);
            }
#pragma unroll
            for (int ci = 0; ci < 16; ci++) {                  // PlVh
                int col = ci * 8 + g;
                uint32_t vh0 = *(const uint32_t*)(sVh + col * VS3 + k0);
                uint32_t vh1 = *(const uint32_t*)(sVh + col * VS3 + k0 + 8);
                mma_bf16(Co[ci], Pl[ks][0], Pl[ks][1], Pl[ks][2], Pl[ks][3], vh0, vh1);
            }
        }
    }

    // ---- write unnormalized partials ----
    size_t rbase = ((size_t)(ksp * NB + b)) * NN + mt * 64;
    size_t r0 = (rbase + rowA) * NCP;
    size_t r1 = (rbase + rowA + 8) * NCP;
#pragma unroll
    for (int ci = 0; ci < 16; ci++) {
        int col = ci * 8 + t * 2;
        *(float2*)(g_Po + r0 + col) = make_float2(Co[ci][0], Co[ci][1]);
        *(float2*)(g_Po + r1 + col) = make_float2(Co[ci][2], Co[ci][3]);
    }
    if (t == 0) {
        g_Pm[rbase + rowA]     = m0;
        g_Pm[rbase + rowA + 8] = m1;
        g_Pl[rbase + rowA]     = l0s;
        g_Pl[rbase + rowA + 8] = l1s;
    }
}

// ============================================================================
// Kernel 4: split-KV combine. out = (O1 w1 + O2 w2)/(l1 w1 + l2 w2) + shortcut.
//   One warp per row; lane handles 4 channels.
// ============================================================================
__global__ void combine_kernel(float* __restrict__ Out)
{
    const int warp = (blockIdx.x * blockDim.x + threadIdx.x) >> 5;
    const int lane = threadIdx.x & 31;
    if (warp >= NB * NN) return;

    float m1 = g_Pm[warp], m2 = g_Pm[NB * NN + warp];
    float l1 = g_Pl[warp], l2 = g_Pl[NB * NN + warp];
    float m = fmaxf(m1, m2);
    float w1 = __expf(m1 - m), w2 = __expf(m2 - m);
    float inv = 1.0f / (l1 * w1 + l2 * w2);

    const float* o1 = g_Po + (size_t)warp * NCP;
    const float* o2 = g_Po + ((size_t)(NB * NN) + warp) * NCP;
    float* out = Out + (size_t)warp * NCP;

    float4 a = *(const float4*)(o1 + lane * 4);
    float4 c = *(const float4*)(o2 + lane * 4);
    float4 s = *(const float4*)(out + lane * 4);
    s.x += (a.x * w1 + c.x * w2) * inv;
    s.y += (a.y * w1 + c.y * w2) * inv;
    s.z += (a.z * w1 + c.z * w2) * inv;
    s.w += (a.w * w1 + c.w * w2) * inv;
    *(float4*)(out + lane * 4) = s;
}

// ============================================================================
// Launch
// ============================================================================
extern "C" void kernel_launch(void* const* d_in, const int* in_sizes, int n_in,
                              void* d_out, int out_size) {
    (void)in_sizes; (void)n_in; (void)out_size;
    const float* x  = (const float*)d_in[0];
    const float* Wk = (const float*)d_in[1];
    const float* bk = (const float*)d_in[2];
    const float* Wq = (const float*)d_in[3];
    const float* bq = (const float*)d_in[4];
    const float* Wv = (const float*)d_in[5];
    const float* bv = (const float*)d_in[6];
    const float* Ws = (const float*)d_in[7];
    const float* bs = (const float*)d_in[8];
    float* out = (float*)d_out;

    cudaFuncSetAttribute(proj_kernel,  cudaFuncAttributeMaxDynamicSharedMemorySize, PRJ_SMEM);
    cudaFuncSetAttribute(flash_kernel, cudaFuncAttributeMaxDynamicSharedMemorySize, FL_SMEM);

    // 0) weight pre-split
    wsplit_kernel<<<4, 256>>>(Wk, Wq, Wv, Ws);
    // 1) projections: K/Q hi-lo, V f32, shortcut -> d_out
    proj_kernel<<<dim3(NB * NN / 128, 4), 256, PRJ_SMEM>>>(x, bk, bq, bv, bs, out);
    // 2) V -> V^T bf16 hi/lo
    vt_kernel<<<dim3(NN / 32, NCP / 32, NB), dim3(32, 8)>>>();
    // 3) flash attention, split-KV partials (512 CTAs, 3/SM)
    flash_kernel<<<dim3(NN / 64, NB, KSPLIT), 128, FL_SMEM>>>();
    // 4) merge partials + shortcut (Out holds shortcut)
    combine_kernel<<<(NB * NN) / 8, 256>>>(out);
}

// round 15
// speedup vs baseline: 1.2754x; 1.2754x over previous
#include <cuda_runtime.h>
#include <cuda_bf16.h>
#include <cstdint>

// Problem constants
#define NB  4
#define NN  4096   // H*W
#define NC  256
#define NCP 128

// Scratch (static __device__ arrays: the sanctioned no-alloc scratch mechanism).
static __device__ float          g_V  [NB * NN * NCP];       // fp32 V
static __device__ __nv_bfloat16  g_Khi[NB * NN * NCP];       // K split hi/lo  [b*NN+n][c]
static __device__ __nv_bfloat16  g_Klo[NB * NN * NCP];
static __device__ __nv_bfloat16  g_Qhi[NB * NN * NCP];       // Q split hi/lo
static __device__ __nv_bfloat16  g_Qlo[NB * NN * NCP];
static __device__ __nv_bfloat16  g_Vthi[NB * NCP * NN];      // V^T hi/lo  [b*NCP+c][n]
static __device__ __nv_bfloat16  g_Vtlo[NB * NCP * NN];
static __device__ __nv_bfloat16  g_Wth[4 * NCP * NC];        // W^T splits [sel][col][k]
static __device__ __nv_bfloat16  g_Wtl[4 * NCP * NC];

// ---- bf16 split + pack helpers ----
__device__ __forceinline__ void bsplit(float x, __nv_bfloat16& h, __nv_bfloat16& l) {
    h = __float2bfloat16(x);
    l = __float2bfloat16(x - __bfloat162float(h));
}
__device__ __forceinline__ uint32_t pk(__nv_bfloat16 a, __nv_bfloat16 b) {
    return (uint32_t)__bfloat16_as_ushort(a) | ((uint32_t)__bfloat16_as_ushort(b) << 16);
}
__device__ __forceinline__ uint32_t pkhi(float a, float b) {
    return pk(__float2bfloat16(a), __float2bfloat16(b));
}
__device__ __forceinline__ uint32_t pklo(float a, float b) {
    __nv_bfloat16 ha = __float2bfloat16(a), hb = __float2bfloat16(b);
    return pk(__float2bfloat16(a - __bfloat162float(ha)),
              __float2bfloat16(b - __bfloat162float(hb)));
}

// ---- warp MMA: m16n8k16, row.col, bf16 in, fp32 acc (baseline PTX, sm_80+) ----
__device__ __forceinline__ void mma_bf16(float c[4], uint32_t a0, uint32_t a1,
                                         uint32_t a2, uint32_t a3,
                                         uint32_t b0, uint32_t b1) {
    asm volatile("mma.sync.aligned.m16n8k16.row.col.f32.bf16.bf16.f32 "
        "{%0,%1,%2,%3}, {%4,%5,%6,%7}, {%8,%9}, {%0,%1,%2,%3};"
        : "+f"(c[0]), "+f"(c[1]), "+f"(c[2]), "+f"(c[3])
        : "r"(a0), "r"(a1), "r"(a2), "r"(a3), "r"(b0), "r"(b1));
}

// ---- ldmatrix x4 (baseline PTX, sm_75+) ----
__device__ __forceinline__ void ldsm_x4(uint32_t& r0, uint32_t& r1,
                                        uint32_t& r2, uint32_t& r3, uint32_t addr) {
    asm volatile("ldmatrix.sync.aligned.m8n8.x4.shared.b16 {%0,%1,%2,%3}, [%4];"
        : "=r"(r0), "=r"(r1), "=r"(r2), "=r"(r3) : "r"(addr));
}
__device__ __forceinline__ uint32_t smem_u32(const void* p) {
    uint32_t a;
    asm("{ .reg .u64 t; cvta.to.shared.u64 t, %1; cvt.u32.u64 %0, t; }" : "=r"(a) : "l"(p));
    return a;
}

#define SKS 72   // 64-wide tile stride (bf16): row 144B = 4-bank shift, LDSM conflict-free
#define KS2 136  // 128-wide tile stride: row 272B = 4-bank shift, LDSM conflict-free

// ============================================================================
// Kernel 0: pre-split + transpose weights.
// ============================================================================
__global__ void wsplit_kernel(const float* __restrict__ Wk, const float* __restrict__ Wq,
                              const float* __restrict__ Wv, const float* __restrict__ Ws)
{
    const int sel = blockIdx.x;
    const float* W = (sel == 0) ? Wk : (sel == 1) ? Wq : (sel == 2) ? Wv : Ws;
    for (int idx = threadIdx.x; idx < NCP * NC; idx += blockDim.x) {
        int c = idx >> 8, k = idx & 255;
        __nv_bfloat16 h, l; bsplit(W[(size_t)k * NCP + c], h, l);
        g_Wth[sel * NCP * NC + idx] = h;
        g_Wtl[sel * NCP * NC + idx] = l;
    }
}

// ============================================================================
// Kernel 1: projections via bf16 mma 3-product split (unchanged).
// ============================================================================
#define PRJ_SMEM (4 * 128 * SKS * 2)   // 73728 B

__global__ void __launch_bounds__(256) proj_kernel(
    const float* __restrict__ X,
    const float* __restrict__ bk, const float* __restrict__ bq,
    const float* __restrict__ bv, const float* __restrict__ bs,
    float* __restrict__ OutS)
{
    extern __shared__ __align__(16) char smraw[];
    __nv_bfloat16* sXh = (__nv_bfloat16*)smraw;
    __nv_bfloat16* sXl = sXh + 128 * SKS;
    __nv_bfloat16* sWh = sXl + 128 * SKS;
    __nv_bfloat16* sWl = sWh + 128 * SKS;

    const int sel = blockIdx.y;
    const float* bia = (sel == 0) ? bk : (sel == 1) ? bq : (sel == 2) ? bv : bs;
    const __nv_bfloat16* Wh = g_Wth + sel * NCP * NC;
    const __nv_bfloat16* Wl = g_Wtl + sel * NCP * NC;

    const int tid = threadIdx.x;
    const int lane = tid & 31, w = tid >> 5;
    const int g = lane >> 2, q4 = lane & 3;
    const int wm = w & 1, wn = w >> 1;
    const int rowBase = blockIdx.x * 128;

    float C[4][4][4];
#pragma unroll
    for (int mi = 0; mi < 4; mi++)
#pragma unroll
        for (int ni = 0; ni < 4; ni++)
#pragma unroll
            for (int e = 0; e < 4; e++) C[mi][ni][e] = 0.f;

    for (int kp = 0; kp < 4; kp++) {
        __syncthreads();
#pragma unroll
        for (int u = 0; u < 8; u++) {
            int idx = tid + u * 256;
            int r = idx >> 4, c4 = idx & 15;
            float4 v = *(const float4*)(X + (size_t)(rowBase + r) * NC + kp * 64 + c4 * 4);
            __nv_bfloat16 h0,l0,h1,l1,h2,l2,h3,l3;
            bsplit(v.x,h0,l0); bsplit(v.y,h1,l1); bsplit(v.z,h2,l2); bsplit(v.w,h3,l3);
            int so = r * SKS + c4 * 4;
            *(uint2*)(sXh + so) = make_uint2(pk(h0,h1), pk(h2,h3));
            *(uint2*)(sXl + so) = make_uint2(pk(l0,l1), pk(l2,l3));
        }
#pragma unroll
        for (int u = 0; u < 4; u++) {
            int idx = tid + u * 256;
            int col = idx >> 3, k8 = idx & 7;
            int go = col * NC + kp * 64 + k8 * 8;
            int so = col * SKS + k8 * 8;
            *(uint4*)(sWh + so) = *(const uint4*)(Wh + go);
            *(uint4*)(sWl + so) = *(const uint4*)(Wl + go);
        }
        __syncthreads();

#pragma unroll
        for (int kc = 0; kc < 4; kc++) {
            const int k0 = kc * 16 + q4 * 2;
            uint32_t Bh[4][2], Bl[4][2];
#pragma unroll
            for (int ni = 0; ni < 4; ni++) {
                int col = wn * 32 + ni * 8 + g;
                Bh[ni][0] = *(const uint32_t*)(sWh + col * SKS + k0);
                Bh[ni][1] = *(const uint32_t*)(sWh + col * SKS + k0 + 8);
                Bl[ni][0] = *(const uint32_t*)(sWl + col * SKS + k0);
                Bl[ni][1] = *(const uint32_t*)(sWl + col * SKS + k0 + 8);
            }
#pragma unroll
            for (int mi = 0; mi < 4; mi++) {
                int row = wm * 64 + mi * 16 + g;
                uint32_t a0 = *(const uint32_t*)(sXh + row * SKS + k0);
                uint32_t a1 = *(const uint32_t*)(sXh + (row + 8) * SKS + k0);
                uint32_t a2 = *(const uint32_t*)(sXh + row * SKS + k0 + 8);
                uint32_t a3 = *(const uint32_t*)(sXh + (row + 8) * SKS + k0 + 8);
                uint32_t l0 = *(const uint32_t*)(sXl + row * SKS + k0);
                uint32_t l1 = *(const uint32_t*)(sXl + (row + 8) * SKS + k0);
                uint32_t l2 = *(const uint32_t*)(sXl + row * SKS + k0 + 8);
                uint32_t l3 = *(const uint32_t*)(sXl + (row + 8) * SKS + k0 + 8);
#pragma unroll
                for (int ni = 0; ni < 4; ni++)
                    mma_bf16(C[mi][ni], a0, a1, a2, a3, Bh[ni][0], Bh[ni][1]); // hh
#pragma unroll
                for (int ni = 0; ni < 4; ni++)
                    mma_bf16(C[mi][ni], a0, a1, a2, a3, Bl[ni][0], Bl[ni][1]); // hl
#pragma unroll
                for (int ni = 0; ni < 4; ni++)
                    mma_bf16(C[mi][ni], l0, l1, l2, l3, Bh[ni][0], Bh[ni][1]); // lh
            }
        }
    }

#pragma unroll
    for (int ni = 0; ni < 4; ni++) {
        int col = wn * 32 + ni * 8 + q4 * 2;
        float2 bb = *(const float2*)(bia + col);
#pragma unroll
        for (int mi = 0; mi < 4; mi++) {
            int row = rowBase + wm * 64 + mi * 16 + g;
            float v0 = C[mi][ni][0] + bb.x, v1 = C[mi][ni][1] + bb.y;
            float v2 = C[mi][ni][2] + bb.x, v3 = C[mi][ni][3] + bb.y;
            size_t o0 = (size_t)row * NCP + col;
            size_t o1 = (size_t)(row + 8) * NCP + col;
            if (sel <= 1) {
                __nv_bfloat16* Yh = (sel == 0) ? g_Khi : g_Qhi;
                __nv_bfloat16* Yl = (sel == 0) ? g_Klo : g_Qlo;
                __nv_bfloat16 h0,l0,h1,l1;
                bsplit(v0,h0,l0); bsplit(v1,h1,l1);
                *(uint32_t*)(Yh + o0) = pk(h0,h1);
                *(uint32_t*)(Yl + o0) = pk(l0,l1);
                bsplit(v2,h0,l0); bsplit(v3,h1,l1);
                *(uint32_t*)(Yh + o1) = pk(h0,h1);
                *(uint32_t*)(Yl + o1) = pk(l0,l1);
            } else {
                float* Yf = (sel == 2) ? g_V : OutS;
                *(float2*)(Yf + o0) = make_float2(v0, v1);
                *(float2*)(Yf + o1) = make_float2(v2, v3);
            }
        }
    }
}

// ============================================================================
// Kernel 2: V -> V^T bf16 hi/lo.
// ============================================================================
__global__ void vt_kernel()
{
    __shared__ float t[32][33];
    const int b  = blockIdx.z;
    const int n0 = blockIdx.x * 32;
    const int c0 = blockIdx.y * 32;
    const int tx = threadIdx.x, ty = threadIdx.y;   // 32 x 8
#pragma unroll
    for (int u = 0; u < 4; u++)
        t[ty * 4 + u][tx] = g_V[((size_t)b * NN + n0 + ty * 4 + u) * NCP + c0 + tx];
    __syncthreads();
#pragma unroll
    for (int u = 0; u < 4; u++) {
        float x = t[tx][ty * 4 + u];
        __nv_bfloat16 h, l; bsplit(x, h, l);
        size_t off = ((size_t)b * NCP + c0 + ty * 4 + u) * NN + n0 + tx;
        g_Vthi[off] = h;
        g_Vtlo[off] = l;
    }
}

// ============================================================================
// Kernel 3: FUSED flash attention (R13 structure: chunk 64, 2 CTAs/SM),
//   fragment loads via ldmatrix.x4 (bit-identical bytes to the LDS.32 path,
//   5x fewer load instructions, conflict-free). bh frags cached across the
//   hh and lh passes.
// ============================================================================
#define FL_SMEM ((4 * 64 * KS2 + 2 * 128 * SKS) * 2)   // 106496 B

__global__ void __launch_bounds__(128) flash_kernel(float* __restrict__ Out)
{
    extern __shared__ __align__(16) char smraw[];
    __nv_bfloat16* sKh = (__nv_bfloat16*)smraw;          // [64][KS2]
    __nv_bfloat16* sKl = sKh + 64 * KS2;
    __nv_bfloat16* sQh = sKl + 64 * KS2;                 // [64][KS2]
    __nv_bfloat16* sQl = sQh + 64 * KS2;
    __nv_bfloat16* sVh = sQl + 64 * KS2;                 // [128][SKS]
    __nv_bfloat16* sVl = sVh + 128 * SKS;

    const int tid = threadIdx.x;
    const int lane = tid & 31, w = tid >> 5;             // 4 warps
    const int g = lane >> 2, t = lane & 3;
    const int l7 = lane & 7, q = lane >> 3;              // ldmatrix lane decomposition
    const int mt = blockIdx.x, b = blockIdx.y;

    // ---- load K tile once (64 rows x 128 d, hi+lo) ----
#pragma unroll
    for (int u = 0; u < 8; u++) {
        int idx = tid + u * 128;
        int r = idx >> 4, c8 = idx & 15;
        size_t go = ((size_t)(b * NN + mt * 64 + r)) * NCP + c8 * 8;
        int so = r * KS2 + c8 * 8;
        *(uint4*)(sKh + so) = *(const uint4*)(g_Khi + go);
        *(uint4*)(sKl + so) = *(const uint4*)(g_Klo + go);
    }

    const int rowA = w * 16 + g;

    // ldmatrix base addresses (bytes). A (K tile): matrices {rows0-7,k0-7},
    // {rows8-15,k0-7}, {rows0-7,k8-15}, {rows8-15,k8-15}.
    const uint32_t aOff = (uint32_t)((w * 16 + l7 + (q & 1) * 8) * (KS2 * 2) + (q >> 1) * 16);
    const uint32_t addrAh = smem_u32(sKh) + aOff;
    const uint32_t addrAl = smem_u32(sKl) + aOff;
    // B (Q / V tiles): matrices {cols0-7,k0-7}, {cols0-7,k8-15},
    // {cols8-15,k0-7}, {cols8-15,k8-15} -> r0,r1 = b0,b1 of col-group, r2,r3 next group.
    const uint32_t bOffQ = (uint32_t)((l7 + (q >> 1) * 8) * (KS2 * 2) + (q & 1) * 16);
    const uint32_t addrQh = smem_u32(sQh) + bOffQ;
    const uint32_t addrQl = smem_u32(sQl) + bOffQ;
    const uint32_t bOffV = (uint32_t)((l7 + (q >> 1) * 8) * (SKS * 2) + (q & 1) * 16);
    const uint32_t addrVh = smem_u32(sVh) + bOffV;
    const uint32_t addrVl = smem_u32(sVl) + bOffV;

    float Co[16][4];
#pragma unroll
    for (int ci = 0; ci < 16; ci++)
#pragma unroll
        for (int e = 0; e < 4; e++) Co[ci][e] = 0.f;
    float m0 = -1e30f, m1 = -1e30f, l0s = 0.f, l1s = 0.f;

    for (int ch = 0; ch < NN / 64; ch++) {
        __syncthreads();
        // Q chunk: 64 q-rows x 128 d
#pragma unroll
        for (int u = 0; u < 8; u++) {
            int idx = tid + u * 128;
            int r = idx >> 4, c8 = idx & 15;
            size_t go = ((size_t)(b * NN + ch * 64 + r)) * NCP + c8 * 8;
            int so = r * KS2 + c8 * 8;
            *(uint4*)(sQh + so) = *(const uint4*)(g_Qhi + go);
            *(uint4*)(sQl + so) = *(const uint4*)(g_Qlo + go);
        }
        // V chunk: 128 c'-rows x 64 n
#pragma unroll
        for (int u = 0; u < 8; u++) {
            int idx = tid + u * 128;
            int r = idx >> 3, c8 = idx & 7;
            size_t go = ((size_t)(b * NCP + r)) * NN + ch * 64 + c8 * 8;
            int so = r * SKS + c8 * 8;
            *(uint4*)(sVh + so) = *(const uint4*)(g_Vthi + go);
            *(uint4*)(sVl + so) = *(const uint4*)(g_Vtlo + go);
        }
        __syncthreads();

        // ---- S tile: passes hh (cache bh) -> lh (cached) -> hl ----
        float Cs[8][4];
#pragma unroll
        for (int ni = 0; ni < 8; ni++)
#pragma unroll
            for (int e = 0; e < 4; e++) Cs[ni][e] = 0.f;
#pragma unroll
        for (int kc = 0; kc < 8; kc++) {
            const uint32_t k32 = kc * 32;
            uint32_t a0, a1, a2, a3, e0, e1, e2, e3;
            ldsm_x4(a0, a1, a2, a3, addrAh + k32);
            ldsm_x4(e0, e1, e2, e3, addrAl + k32);
            uint32_t bhr[4][4];
#pragma unroll
            for (int np = 0; np < 4; np++) {                       // hh + cache bh
                ldsm_x4(bhr[np][0], bhr[np][1], bhr[np][2], bhr[np][3],
                        addrQh + np * (16 * KS2 * 2) + k32);
                mma_bf16(Cs[2*np],   a0, a1, a2, a3, bhr[np][0], bhr[np][1]);
                mma_bf16(Cs[2*np+1], a0, a1, a2, a3, bhr[np][2], bhr[np][3]);
            }
#pragma unroll
            for (int np = 0; np < 4; np++) {                       // lh (cached bh)
                mma_bf16(Cs[2*np],   e0, e1, e2, e3, bhr[np][0], bhr[np][1]);
                mma_bf16(Cs[2*np+1], e0, e1, e2, e3, bhr[np][2], bhr[np][3]);
            }
#pragma unroll
            for (int np = 0; np < 4; np++) {                       // hl
                uint32_t b0, b1, b2, b3;
                ldsm_x4(b0, b1, b2, b3, addrQl + np * (16 * KS2 * 2) + k32);
                mma_bf16(Cs[2*np],   a0, a1, a2, a3, b0, b1);
                mma_bf16(Cs[2*np+1], a0, a1, a2, a3, b2, b3);
            }
        }

        // ---- online softmax (rows g and g+8; row spread over 4 t-lanes) ----
        float mx0 = -1e30f, mx1 = -1e30f;
#pragma unroll
        for (int ni = 0; ni < 8; ni++) {
            mx0 = fmaxf(mx0, fmaxf(Cs[ni][0], Cs[ni][1]));
            mx1 = fmaxf(mx1, fmaxf(Cs[ni][2], Cs[ni][3]));
        }
        mx0 = fmaxf(mx0, __shfl_xor_sync(0xffffffffu, mx0, 1));
        mx0 = fmaxf(mx0, __shfl_xor_sync(0xffffffffu, mx0, 2));
        mx1 = fmaxf(mx1, __shfl_xor_sync(0xffffffffu, mx1, 1));
        mx1 = fmaxf(mx1, __shfl_xor_sync(0xffffffffu, mx1, 2));
        float mn0 = fmaxf(m0, mx0), mn1 = fmaxf(m1, mx1);
        if (mn0 > m0 || mn1 > m1) {
            float al0 = __expf(m0 - mn0), al1 = __expf(m1 - mn1);
            l0s *= al0; l1s *= al1;
#pragma unroll
            for (int ci = 0; ci < 16; ci++) {
                Co[ci][0] *= al0; Co[ci][1] *= al0;
                Co[ci][2] *= al1; Co[ci][3] *= al1;
            }
            m0 = mn0; m1 = mn1;
        }
        float s0 = 0.f, s1 = 0.f;
#pragma unroll
        for (int ni = 0; ni < 8; ni++) {
            Cs[ni][0] = __expf(Cs[ni][0] - m0);
            Cs[ni][1] = __expf(Cs[ni][1] - m0);
            Cs[ni][2] = __expf(Cs[ni][2] - m1);
            Cs[ni][3] = __expf(Cs[ni][3] - m1);
            s0 += Cs[ni][0] + Cs[ni][1];
            s1 += Cs[ni][2] + Cs[ni][3];
        }
        s0 += __shfl_xor_sync(0xffffffffu, s0, 1);
        s0 += __shfl_xor_sync(0xffffffffu, s0, 2);
        s1 += __shfl_xor_sync(0xffffffffu, s1, 1);
        s1 += __shfl_xor_sync(0xffffffffu, s1, 2);
        l0s += s0;
        l1s += s1;

        // ---- build P A-frags (C-frag == A-frag identity) ----
        uint32_t Ph[4][4], Pl[4][4];
#pragma unroll
        for (int ki = 0; ki < 4; ki++) {
            Ph[ki][0] = pkhi(Cs[2*ki  ][0], Cs[2*ki  ][1]);
            Ph[ki][1] = pkhi(Cs[2*ki  ][2], Cs[2*ki  ][3]);
            Ph[ki][2] = pkhi(Cs[2*ki+1][0], Cs[2*ki+1][1]);
            Ph[ki][3] = pkhi(Cs[2*ki+1][2], Cs[2*ki+1][3]);
            Pl[ki][0] = pklo(Cs[2*ki  ][0], Cs[2*ki  ][1]);
            Pl[ki][1] = pklo(Cs[2*ki  ][2], Cs[2*ki  ][3]);
            Pl[ki][2] = pklo(Cs[2*ki+1][0], Cs[2*ki+1][1]);
            Pl[ki][3] = pklo(Cs[2*ki+1][2], Cs[2*ki+1][3]);
        }

        // ---- O += P @ V: product-outer passes, ldmatrix loads ----
#pragma unroll
        for (int ks = 0; ks < 4; ks++) {
            const uint32_t k32 = ks * 32;
#pragma unroll
            for (int cp = 0; cp < 8; cp++) {                       // PhVh
                uint32_t v0, v1, v2, v3;
                ldsm_x4(v0, v1, v2, v3, addrVh + cp * (16 * SKS * 2) + k32);
                mma_bf16(Co[2*cp],   Ph[ks][0], Ph[ks][1], Ph[ks][2], Ph[ks][3], v0, v1);
                mma_bf16(Co[2*cp+1], Ph[ks][0], Ph[ks][1], Ph[ks][2], Ph[ks][3], v2, v3);
            }
#pragma unroll
            for (int cp = 0; cp < 8; cp++) {                       // PhVl
                uint32_t v0, v1, v2, v3;
                ldsm_x4(v0, v1, v2, v3, addrVl + cp * (16 * SKS * 2) + k32);
                mma_bf16(Co[2*cp],   Ph[ks][0], Ph[ks][1], Ph[ks][2], Ph[ks][3], v0, v1);
                mma_bf16(Co[2*cp+1], Ph[ks][0], Ph[ks][1], Ph[ks][2], Ph[ks][3], v2, v3);
            }
#pragma unroll
            for (int cp = 0; cp < 8; cp++) {                       // PlVh
                uint32_t v0, v1, v2, v3;
                ldsm_x4(v0, v1, v2, v3, addrVh + cp * (16 * SKS * 2) + k32);
                mma_bf16(Co[2*cp],   Pl[ks][0], Pl[ks][1], Pl[ks][2], Pl[ks][3], v0, v1);
                mma_bf16(Co[2*cp+1], Pl[ks][0], Pl[ks][1], Pl[ks][2], Pl[ks][3], v2, v3);
            }
        }
    }

    // ---- epilogue: Out = O/l + shortcut (Out holds shortcut) ----
    float i0 = 1.0f / l0s, i1 = 1.0f / l1s;
    size_t r0 = (size_t)(b * NN + mt * 64 + rowA) * NCP;
    size_t r1 = (size_t)(b * NN + mt * 64 + rowA + 8) * NCP;
#pragma unroll
    for (int ci = 0; ci < 16; ci++) {
        int col = ci * 8 + t * 2;
        float2 s0v = *(float2*)(Out + r0 + col);
        float2 s1v = *(float2*)(Out + r1 + col);
        *(float2*)(Out + r0 + col) = make_float2(Co[ci][0] * i0 + s0v.x,
                                                 Co[ci][1] * i0 + s0v.y);
        *(float2*)(Out + r1 + col) = make_float2(Co[ci][2] * i1 + s1v.x,
                                                 Co[ci][3] * i1 + s1v.y);
    }
}

// ============================================================================
// Launch
// ============================================================================
extern "C" void kernel_launch(void* const* d_in, const int* in_sizes, int n_in,
                              void* d_out, int out_size) {
    (void)in_sizes; (void)n_in; (void)out_size;
    const float* x  = (const float*)d_in[0];
    const float* Wk = (const float*)d_in[1];
    const float* bk = (const float*)d_in[2];
    const float* Wq = (const float*)d_in[3];
    const float* bq = (const float*)d_in[4];
    const float* Wv = (const float*)d_in[5];
    const float* bv = (const float*)d_in[6];
    const float* Ws = (const float*)d_in[7];
    const float* bs = (const float*)d_in[8];
    float* out = (float*)d_out;

    cudaFuncSetAttribute(proj_kernel,  cudaFuncAttributeMaxDynamicSharedMemorySize, PRJ_SMEM);
    cudaFuncSetAttribute(flash_kernel, cudaFuncAttributeMaxDynamicSharedMemorySize, FL_SMEM);

    // 0) weight pre-split
    wsplit_kernel<<<4, 256>>>(Wk, Wq, Wv, Ws);
    // 1) projections: K/Q hi-lo, V f32, shortcut -> d_out
    proj_kernel<<<dim3(NB * NN / 128, 4), 256, PRJ_SMEM>>>(x, bk, bq, bv, bs, out);
    // 2) V -> V^T bf16 hi/lo
    vt_kernel<<<dim3(NN / 32, NCP / 32, NB), dim3(32, 8)>>>();
    // 3) fused flash attention (+ shortcut add), R13 grid
    flash_kernel<<<dim3(NN / 64, NB), 128, FL_SMEM>>>(out);
}